// round 1
// baseline (speedup 1.0000x reference)
#include <cuda_runtime.h>

// RoiAlign: feature_map [B=8,H=64,W=64,C=256] f32, rpn_pred [B,N=512,4] f32 (x1,y1,x2,y2 normalized)
// out [B,N,7,7,C] f32. TF crop_and_resize bilinear semantics.

#define B_ 8
#define H_ 64
#define W_ 64
#define C_ 256
#define N_ 512
#define POOL_ 7

__global__ void roi_align_kernel(const float* __restrict__ fm,
                                 const float* __restrict__ boxes,
                                 float* __restrict__ out) {
    // blockDim = (64, 4): 64 lanes x float4 = 256 channels; 4 pool positions per block
    const int pos = blockIdx.y * 4 + threadIdx.y;   // 0..51, valid 0..48
    if (pos >= POOL_ * POOL_) return;
    const int box = blockIdx.x;                     // 0..4095  (b*512 + n)
    const int b = box >> 9;

    const float4 bx = __ldg((const float4*)(boxes + (size_t)box * 4));
    const float x1 = bx.x, y1 = bx.y, x2 = bx.z, y2 = bx.w;

    const int py = pos / POOL_;
    const int px = pos - py * POOL_;

    const float ys = y1 * (H_ - 1) + (float)py * ((y2 - y1) * (H_ - 1) / (POOL_ - 1));
    const float xs = x1 * (W_ - 1) + (float)px * ((x2 - x1) * (W_ - 1) / (POOL_ - 1));

    const float yf = floorf(ys);
    const float xf = floorf(xs);
    const float fy = ys - yf;
    const float fx = xs - xf;

    int yt = (int)yf;
    int xl = (int)xf;
    int yb = yt + 1;
    int xr = xl + 1;
    yt = min(max(yt, 0), H_ - 1);
    yb = min(max(yb, 0), H_ - 1);
    xl = min(max(xl, 0), W_ - 1);
    xr = min(max(xr, 0), W_ - 1);

    const bool valid = (ys >= 0.f) && (ys <= (float)(H_ - 1)) &&
                       (xs >= 0.f) && (xs <= (float)(W_ - 1));

    const int c = threadIdx.x * 4;  // channel offset (float4)
    const float* base = fm + (size_t)b * H_ * W_ * C_;

    const float4 tl = __ldg((const float4*)(base + ((size_t)yt * W_ + xl) * C_ + c));
    const float4 tr = __ldg((const float4*)(base + ((size_t)yt * W_ + xr) * C_ + c));
    const float4 bl = __ldg((const float4*)(base + ((size_t)yb * W_ + xl) * C_ + c));
    const float4 br = __ldg((const float4*)(base + ((size_t)yb * W_ + xr) * C_ + c));

    float4 o;
    {
        float top, bot;
        top = tl.x + (tr.x - tl.x) * fx; bot = bl.x + (br.x - bl.x) * fx; o.x = top + (bot - top) * fy;
        top = tl.y + (tr.y - tl.y) * fx; bot = bl.y + (br.y - bl.y) * fx; o.y = top + (bot - top) * fy;
        top = tl.z + (tr.z - tl.z) * fx; bot = bl.z + (br.z - bl.z) * fx; o.z = top + (bot - top) * fy;
        top = tl.w + (tr.w - tl.w) * fx; bot = bl.w + (br.w - bl.w) * fx; o.w = top + (bot - top) * fy;
    }
    if (!valid) { o.x = 0.f; o.y = 0.f; o.z = 0.f; o.w = 0.f; }

    float* op = out + (((size_t)box * (POOL_ * POOL_) + pos) * C_ + c);
    *(float4*)op = o;
}

extern "C" void kernel_launch(void* const* d_in, const int* in_sizes, int n_in,
                              void* d_out, int out_size) {
    const float* fm    = (const float*)d_in[0];   // [8,64,64,256]
    const float* boxes = (const float*)d_in[1];   // [8,512,4]
    float* out = (float*)d_out;                   // [8,512,7,7,256]

    dim3 block(64, 4);
    dim3 grid(B_ * N_, (POOL_ * POOL_ + 3) / 4);  // (4096, 13)
    roi_align_kernel<<<grid, block>>>(fm, boxes, out);
}